// round 16
// baseline (speedup 1.0000x reference)
#include <cuda_runtime.h>
#include <cuda_fp16.h>
#include <cstdint>

// ============================================================================
// node_s (4096x256) = X_s (4096x4096) @ C_s^T, single fp16 product.
//   skip0: rows (b,n0), k=(n1,n2) -> A rows from g_xh straight
//   skip1: rows (b,n1), k=(n0,n2) -> gather 64-row blocks of g_xh (2 b per CTA)
//   skip2: rows (b,n2), k=(n1,n0) -> A^T tiles from g_xh + ldmatrix.trans
// SPLIT-K x4; BM=128 BN=128, 256 thr (8 warps 2x4, warp tile 64x32), 4-stage
// cp.async (load-ahead 3). Partials -> g_part; 4th-arriving CTA per tile
// (threadfence+ticket) sums partials -> out. prep+chain fused kernel.
// ============================================================================

#define BM 128
#define BN 128
#define KCHUNKS_QTR 32              // 1024 K per quarter, chunks of 32
#define PITCH 80                    // A/B rows: 64B + 16B pad
#define TPITCH 272                  // skip2 A^T rows: 256B + 16B pad
#define APART (BM * PITCH)          // 10240 (skip2 uses 32*272=8704 of it)
#define STAGE_BYTES (APART + BN * PITCH)  // 20480
#define NSTAGE 4
#define SMEM_TOTAL (STAGE_BYTES * NSTAGE)  // 81920

// ---- scratch (device globals: no allocation) ----
__device__ __align__(1024) __half g_xh[16777216];        // [b][n0][n1][n2]
__device__ __align__(1024) __half g_c[3u * 256 * 4096];  // chains [s][pq][k]
__device__ __align__(1024) float g_part[4u * 3145728];   // [kq][skip][m][n]
__device__ unsigned int g_ticket[384];                   // [skip][mtile][ntile]

// ---- PTX helpers ----
__device__ __forceinline__ uint32_t smem_u32(const void* p) {
    uint32_t a;
    asm("{ .reg .u64 t; cvta.to.shared.u64 t, %1; cvt.u32.u64 %0, t; }" : "=r"(a) : "l"(p));
    return a;
}
__device__ __forceinline__ void cp_async16(uint32_t s, const void* g) {
    asm volatile("cp.async.cg.shared.global [%0], [%1], 16;\n" :: "r"(s), "l"(g));
}
__device__ __forceinline__ void cp_commit() { asm volatile("cp.async.commit_group;\n" ::: "memory"); }
template <int N> __device__ __forceinline__ void cp_wait() {
    asm volatile("cp.async.wait_group %0;\n" :: "n"(N) : "memory");
}
__device__ __forceinline__ void ldsm_x4(uint32_t& r0, uint32_t& r1, uint32_t& r2,
                                        uint32_t& r3, uint32_t addr) {
    asm volatile("ldmatrix.sync.aligned.m8n8.x4.shared.b16 {%0,%1,%2,%3}, [%4];"
                 : "=r"(r0), "=r"(r1), "=r"(r2), "=r"(r3) : "r"(addr));
}
__device__ __forceinline__ void ldsm_x4_t(uint32_t& r0, uint32_t& r1, uint32_t& r2,
                                          uint32_t& r3, uint32_t addr) {
    asm volatile("ldmatrix.sync.aligned.m8n8.x4.trans.shared.b16 {%0,%1,%2,%3}, [%4];"
                 : "=r"(r0), "=r"(r1), "=r"(r2), "=r"(r3) : "r"(addr));
}
__device__ __forceinline__ void mma16816(float* d, const uint32_t* a, uint32_t b0, uint32_t b1) {
    asm volatile("mma.sync.aligned.m16n8k16.row.col.f32.f16.f16.f32 "
                 "{%0,%1,%2,%3},{%4,%5,%6,%7},{%8,%9},{%0,%1,%2,%3};"
                 : "+f"(d[0]), "+f"(d[1]), "+f"(d[2]), "+f"(d[3])
                 : "r"(a[0]), "r"(a[1]), "r"(a[2]), "r"(a[3]), "r"(b0), "r"(b1));
}

// ============================================================================
// prep+chain fused, grid 5632 x 256 (unchanged from round 15).
// ============================================================================
__global__ void __launch_bounds__(256) prep_chain_kernel(const float* __restrict__ x,
                                                         const float* __restrict__ c0,
                                                         const float* __restrict__ c1,
                                                         const float* __restrict__ c2) {
    const int tid = threadIdx.x;
    if (blockIdx.x < 4096) {
        const size_t i = ((size_t)blockIdx.x * 256 + tid) * 16;
        __half hb[16];
#pragma unroll
        for (int j = 0; j < 4; j++) {
            float4 q = *(const float4*)(x + i + j * 4);
            hb[j * 4 + 0] = __float2half_rn(q.x);
            hb[j * 4 + 1] = __float2half_rn(q.y);
            hb[j * 4 + 2] = __float2half_rn(q.z);
            hb[j * 4 + 3] = __float2half_rn(q.w);
        }
        *(float4*)(g_xh + i) = ((const float4*)hb)[0];
        *(float4*)(g_xh + i + 8) = ((const float4*)hb)[1];
    } else {
        const int idx = blockIdx.x - 4096;
        const int s = idx >> 9, u = (idx & 511) >> 3, vg = idx & 7;
        const int p = tid >> 4, q = tid & 15;
        __shared__ float U[256], V[8][256];
        const float* Uc = (s == 1) ? c0 : c1;
        const float* Vc = (s == 2) ? c0 : c2;
        U[tid] = Uc[u * 256 + tid];
#pragma unroll
        for (int j = 0; j < 8; j++) V[j][tid] = Vc[(vg * 8 + j) * 256 + tid];
        __syncthreads();

        __half vals[8];
#pragma unroll
        for (int j = 0; j < 8; j++) {
            float acc = 0.f;
            if (s == 0) {
#pragma unroll
                for (int t = 0; t < 16; t++) acc += U[p * 16 + t] * V[j][t * 16 + q];
            } else {
#pragma unroll
                for (int t = 0; t < 16; t++) acc += V[j][p * 16 + t] * U[t * 16 + q];
            }
            vals[j] = __float2half_rn(acc);
        }
        const size_t o = (size_t)s * 1048576 + (size_t)tid * 4096 + (size_t)u * 64 + vg * 8;
        *(float4*)(g_c + o) = *(const float4*)vals;
    }
}

// ============================================================================
// GEMM: grid(32 m, 2 n, 12 = skip*4 + kq), 256 threads (8 warps 2x4,
// warp tile 64x32). K chunks [kq*32, kq*32+32). 4-stage, load-ahead 3.
// ============================================================================
template <int SKIP>
__device__ __forceinline__ void gemm_body(float* __restrict__ out,
                                          float* __restrict__ part, int kbase,
                                          unsigned* s_old) {
    extern __shared__ char smem[];
    const uint32_t sb = smem_u32(smem);
    const int tid = threadIdx.x, lane = tid & 31, wid = tid >> 5;
    const int wm = wid >> 2, wn = wid & 3;
    const int m0 = blockIdx.x * BM, n0 = blockIdx.y * BN;

    const __half* B = g_c + (size_t)SKIP * 1048576;

    auto load = [&](int chunk, int st) {  // chunk: global 0..127
        const uint32_t stg = sb + st * STAGE_BYTES;
        if (SKIP == 2) {
            // A^T tile: 32 k-rows (n0) x 128 m (b_local*64 + n2), rows 256B
            const int bb = m0 >> 6;
#pragma unroll
            for (int i = 0; i < 2; i++) {
                const int lin = tid + i * 256;
                const int r = lin >> 4, c = lin & 15;  // r: k-row, c: 16B seg
                const __half* g = g_xh + ((size_t)(bb + (c >> 3)) << 18) +
                                  ((size_t)(((chunk & 1) << 5) + r) << 12) +
                                  ((chunk >> 1) << 6) + ((c & 7) << 3);
                cp_async16(stg + r * TPITCH + c * 16, g);
            }
        } else {
#pragma unroll
            for (int i = 0; i < 2; i++) {
                const int lin = tid + i * 256;
                const int r = lin >> 2, c = lin & 3;
                size_t offA;
                if (SKIP == 1) {
                    const int bb = (m0 >> 6) + (r >> 6);
                    offA = ((size_t)bb << 18) + ((size_t)(chunk >> 1) << 12) +
                           ((r & 63) << 6) + ((chunk & 1) << 5) + (c << 3);
                } else {
                    offA = ((size_t)(m0 + r) << 12) + (chunk << 5) + (c << 3);
                }
                cp_async16(stg + r * PITCH + c * 16, g_xh + offA);
            }
        }
#pragma unroll
        for (int i = 0; i < 2; i++) {
            const int lin = tid + i * 256;
            const int r = lin >> 2, c = lin & 3;
            cp_async16(stg + APART + r * PITCH + c * 16,
                       B + ((size_t)(n0 + r) << 12) + (chunk << 5) + (c << 3));
        }
        cp_commit();
    };

    float acc[4][4][4];
#pragma unroll
    for (int fm = 0; fm < 4; fm++)
#pragma unroll
        for (int fn = 0; fn < 4; fn++)
#pragma unroll
            for (int j = 0; j < 4; j++) acc[fm][fn][j] = 0.f;

    load(kbase + 0, 0);
    load(kbase + 1, 1);
    load(kbase + 2, 2);

    const uint32_t aoff = (wm * 64 + (lane & 15)) * PITCH + (lane >> 4) * 16;   // skips 0,1
    const uint32_t atoff = ((lane & 7) + ((lane >> 4) << 3)) * TPITCH +
                           ((lane >> 3) & 1) * 16 + wm * 128;                    // skip 2 (trans)
    const uint32_t boff = APART + (wn * 32 + (lane & 15)) * PITCH + (lane >> 4) * 16;

    for (int c = 0; c < KCHUNKS_QTR; c++) {
        const int st = c & 3;
        if (c <= KCHUNKS_QTR - 3)      cp_wait<2>();
        else if (c == KCHUNKS_QTR - 2) cp_wait<1>();
        else                           cp_wait<0>();
        __syncthreads();  // data(c) ready AND all warps done with stage (c-1)&3
        if (c + 3 < KCHUNKS_QTR) load(kbase + c + 3, (c + 3) & 3);

        const uint32_t stg = sb + st * STAGE_BYTES;
#pragma unroll
        for (int ks = 0; ks < 2; ks++) {
            uint32_t b[2][4];
#pragma unroll
            for (int fp = 0; fp < 2; fp++)
                ldsm_x4(b[fp][0], b[fp][1], b[fp][2], b[fp][3],
                        stg + boff + fp * (16 * PITCH) + ks * 32);
#pragma unroll
            for (int fm = 0; fm < 4; fm++) {
                uint32_t a4[4];
                if (SKIP == 2)
                    ldsm_x4_t(a4[0], a4[1], a4[2], a4[3],
                              stg + atoff + ks * (16 * TPITCH) + fm * 32);
                else
                    ldsm_x4(a4[0], a4[1], a4[2], a4[3],
                            stg + aoff + fm * (16 * PITCH) + ks * 32);
#pragma unroll
                for (int fn = 0; fn < 4; fn++)
                    mma16816(acc[fm][fn], a4, b[fn >> 1][fn & 1], b[fn >> 1][(fn & 1) + 2]);
            }
        }
    }

    // ---- epilogue: store this quarter's partial (plain stores, idempotent) ----
    const int rbase = m0 + wm * 64 + (lane >> 2);
    const int cbase = n0 + wn * 32 + (lane & 3) * 2;
#pragma unroll
    for (int fm = 0; fm < 4; fm++)
#pragma unroll
        for (int fn = 0; fn < 4; fn++) {
            const int rr = rbase + fm * 16;
            const int cc = cbase + fn * 8;
            *(float2*)(part + (size_t)rr * 256 + cc) = make_float2(acc[fm][fn][0], acc[fm][fn][1]);
            *(float2*)(part + (size_t)(rr + 8) * 256 + cc) = make_float2(acc[fm][fn][2], acc[fm][fn][3]);
        }

    // ---- ticket: 4th arrival for this (skip, mtile, ntile) combines -> out ----
    __threadfence();
    __syncthreads();
    if (tid == 0)
        *s_old = atomicAdd(&g_ticket[SKIP * 64 + blockIdx.x * 2 + blockIdx.y], 1u);
    __syncthreads();
    if ((*s_old & 3u) == 3u) {
        __threadfence();
        const float* p0 = g_part + (size_t)SKIP * 1048576;
        float* outp = out + (size_t)SKIP * 1048576;
#pragma unroll
        for (int it = 0; it < 16; it++) {
            const int lin = tid + it * 256;
            const int row = lin >> 5, c4 = (lin & 31) * 4;
            const size_t off = (size_t)(m0 + row) * 256 + n0 + c4;
            float4 a = *(const float4*)(p0 + off);
            float4 b = *(const float4*)(p0 + 3145728 + off);
            float4 cc = *(const float4*)(p0 + 2u * 3145728 + off);
            float4 d = *(const float4*)(p0 + 3u * 3145728 + off);
            *(float4*)(outp + off) = make_float4((a.x + b.x) + (cc.x + d.x),
                                                 (a.y + b.y) + (cc.y + d.y),
                                                 (a.z + b.z) + (cc.z + d.z),
                                                 (a.w + b.w) + (cc.w + d.w));
        }
    }
}

__global__ void __launch_bounds__(256, 2) gemm_kernel(float* __restrict__ out) {
    __shared__ unsigned s_old;
    const int skip = blockIdx.z >> 2;
    const int kq = blockIdx.z & 3;
    float* part = g_part + (size_t)kq * 3145728 + (size_t)skip * 1048576;
    const int kbase = kq * KCHUNKS_QTR;
    if (skip == 0)      gemm_body<0>(out, part, kbase, &s_old);
    else if (skip == 1) gemm_body<1>(out, part, kbase, &s_old);
    else                gemm_body<2>(out, part, kbase, &s_old);
}

// ----------------------------------------------------------------------------
extern "C" void kernel_launch(void* const* d_in, const int* in_sizes, int n_in,
                              void* d_out, int out_size) {
    const float* x  = (const float*)d_in[0];
    const float* c0 = (const float*)d_in[1];
    const float* c1 = (const float*)d_in[2];
    const float* c2 = (const float*)d_in[3];
    float* out = (float*)d_out;

    cudaFuncSetAttribute(gemm_kernel, cudaFuncAttributeMaxDynamicSharedMemorySize, SMEM_TOTAL);
    prep_chain_kernel<<<5632, 256>>>(x, c0, c1, c2);
    gemm_kernel<<<dim3(32, 2, 12), 256, SMEM_TOTAL>>>(out);
}